// round 2
// baseline (speedup 1.0000x reference)
#include <cuda_runtime.h>
#include <math.h>

#define Tt 1024
#define Bb 16
#define Dd 1024
#define NBLK 128
#define OUT_OFS (Tt*Bb*Dd)

__device__ __align__(16) float g_pre[Tt*Bb*Dd];
__device__ __align__(16) float g_h[2][Bb*Dd];
__device__ __align__(16) float g_scale[Dd];
__device__ unsigned g_arrive;

__device__ __forceinline__ float blockReduceSum(float v) {
    __shared__ float red[32];
    int lane = threadIdx.x & 31, wid = threadIdx.x >> 5;
#pragma unroll
    for (int o = 16; o > 0; o >>= 1) v += __shfl_down_sync(0xffffffffu, v, o);
    if (lane == 0) red[wid] = v;
    __syncthreads();
    int nw = blockDim.x >> 5;
    if (wid == 0) {
        v = (lane < nw) ? red[lane] : 0.f;
#pragma unroll
        for (int o = 16; o > 0; o >>= 1) v += __shfl_down_sync(0xffffffffu, v, o);
    }
    return v; // valid in thread 0
}

// ---- init: h buffers + barrier counter + h_all[0] ----
__global__ void k_init(const float* __restrict__ h0, float* __restrict__ hall) {
    int tid = blockIdx.x * blockDim.x + threadIdx.x;
    if (tid == 0) g_arrive = 0u;
    for (int i = tid; i < Bb*Dd; i += gridDim.x * blockDim.x) {
        float v = h0[i];
        g_h[0][i] = v;
        hall[i] = v;
    }
}

// ---- power iteration + sigma + per-row scale (single block, 1024 thr) ----
__global__ void __launch_bounds__(1024) k_prep(const float* __restrict__ Wh,
                                               const float* __restrict__ lr,
                                               const float* __restrict__ u0) {
    __shared__ __align__(16) float su[Dd], sv[Dd], stmp[Dd];
    __shared__ float s_bc, s_sig;
    int t = threadIdx.x, w = t >> 5, l = t & 31;
    su[t] = u0[t];
    __syncthreads();
    for (int it = 0; it < 3; it++) {
        // tmp = Wh^T @ u : 256 threads, 4 cols each (coalesced float4)
        if (t < 256) {
            float4 acc = make_float4(0.f,0.f,0.f,0.f);
            const float* p = Wh + 4*t;
            for (int i = 0; i < Dd; i++) {
                float u = su[i];
                float4 wv = *(const float4*)(p + (size_t)i * Dd);
                acc.x += u*wv.x; acc.y += u*wv.y; acc.z += u*wv.z; acc.w += u*wv.w;
            }
            *(float4*)&stmp[4*t] = acc;
        }
        __syncthreads();
        float x = stmp[t];
        float s = blockReduceSum(x * x);
        if (t == 0) s_bc = 1.f / (sqrtf(s) + 1e-8f);
        __syncthreads();
        sv[t] = stmp[t] * s_bc;
        __syncthreads();
        // tmp = Wh @ v : warp per 32 rows
        for (int rr = 0; rr < 32; rr++) {
            int r = w * 32 + rr;
            float acc = 0.f;
            const float* row = Wh + (size_t)r * Dd;
#pragma unroll
            for (int c = 0; c < 8; c++) {
                int f4 = c * 32 + l;
                float4 a = *(const float4*)(row + 4*f4);
                float4 b = *(const float4*)&sv[4*f4];
                acc += a.x*b.x + a.y*b.y + a.z*b.z + a.w*b.w;
            }
#pragma unroll
            for (int o = 16; o > 0; o >>= 1) acc += __shfl_xor_sync(0xffffffffu, acc, o);
            if (l == 0) stmp[r] = acc;
        }
        __syncthreads();
        x = stmp[t];
        s = blockReduceSum(x * x);
        if (t == 0) {
            s_bc = 1.f / (sqrtf(s) + 1e-8f);
            if (it == 2) s_sig = s / (sqrtf(s) + 1e-8f);  // sigma = u.(Wv)
        }
        __syncthreads();
        su[t] = stmp[t] * s_bc;
        __syncthreads();
    }
    float radius = 0.999f / (1.f + expf(-lr[t]));
    g_scale[t] = radius / (s_sig + 1e-8f);
}

// ---- GEMM: g_pre[m,n] = x[m,:].Wx[n,:] + b[n]   (128x128x8 double-buffered) ----
__global__ void __launch_bounds__(256) k_gemm(const float* __restrict__ A,
                                              const float* __restrict__ Bw,
                                              const float* __restrict__ bias) {
    __shared__ float As[2][8][132], Bs[2][8][132];
    int tid = threadIdx.x;
    int m0 = blockIdx.y << 7, n0 = blockIdx.x << 7;
    int srow = tid >> 1, skq = (tid & 1) << 2;
    const float* ap = A  + (size_t)(m0 + srow) * Dd + skq;
    const float* bp = Bw + (size_t)(n0 + srow) * Dd + skq;
    int tx = tid & 15, ty = tid >> 4;

    float4 a4 = *(const float4*)ap;
    float4 b4 = *(const float4*)bp;
    As[0][skq+0][srow]=a4.x; As[0][skq+1][srow]=a4.y; As[0][skq+2][srow]=a4.z; As[0][skq+3][srow]=a4.w;
    Bs[0][skq+0][srow]=b4.x; Bs[0][skq+1][srow]=b4.y; Bs[0][skq+2][srow]=b4.z; Bs[0][skq+3][srow]=b4.w;
    __syncthreads();

    float acc[8][8];
#pragma unroll
    for (int r = 0; r < 8; r++)
#pragma unroll
        for (int c = 0; c < 8; c++) acc[r][c] = 0.f;

    for (int kt = 0; kt < 128; kt++) {
        int cur = kt & 1;
        float4 a4n, b4n;
        if (kt < 127) {
            a4n = *(const float4*)(ap + (size_t)(kt+1)*8);
            b4n = *(const float4*)(bp + (size_t)(kt+1)*8);
        }
#pragma unroll
        for (int k = 0; k < 8; k++) {
            float4 a0 = *(const float4*)&As[cur][k][ty<<2];
            float4 a1 = *(const float4*)&As[cur][k][64+(ty<<2)];
            float4 b0 = *(const float4*)&Bs[cur][k][tx<<2];
            float4 b1 = *(const float4*)&Bs[cur][k][64+(tx<<2)];
            float ar[8] = {a0.x,a0.y,a0.z,a0.w,a1.x,a1.y,a1.z,a1.w};
            float br[8] = {b0.x,b0.y,b0.z,b0.w,b1.x,b1.y,b1.z,b1.w};
#pragma unroll
            for (int r = 0; r < 8; r++)
#pragma unroll
                for (int c = 0; c < 8; c++) acc[r][c] += ar[r]*br[c];
        }
        if (kt < 127) {
            int nb = cur ^ 1;
            __syncthreads();
            As[nb][skq+0][srow]=a4n.x; As[nb][skq+1][srow]=a4n.y; As[nb][skq+2][srow]=a4n.z; As[nb][skq+3][srow]=a4n.w;
            Bs[nb][skq+0][srow]=b4n.x; Bs[nb][skq+1][srow]=b4n.y; Bs[nb][skq+2][srow]=b4n.z; Bs[nb][skq+3][srow]=b4n.w;
            __syncthreads();
        }
    }
    float4 ba0 = *(const float4*)&bias[n0 + (tx<<2)];
    float4 ba1 = *(const float4*)&bias[n0 + 64 + (tx<<2)];
#pragma unroll
    for (int r = 0; r < 8; r++) {
        int m = m0 + ((r < 4) ? (ty<<2)+r : 64+(ty<<2)+r-4);
        float* o = g_pre + (size_t)m * Dd + n0;
        float4 v0 = make_float4(acc[r][0]+ba0.x, acc[r][1]+ba0.y, acc[r][2]+ba0.z, acc[r][3]+ba0.w);
        float4 v1 = make_float4(acc[r][4]+ba1.x, acc[r][5]+ba1.y, acc[r][6]+ba1.z, acc[r][7]+ba1.w);
        *(float4*)(o + (tx<<2)) = v0;
        *(float4*)(o + 64 + (tx<<2)) = v1;
    }
}

// ---- persistent recurrence: 128 blocks x 256 threads ----
__global__ void __launch_bounds__(256) k_recur(const float* __restrict__ Wh,
                                               const float* __restrict__ z,
                                               float* __restrict__ outp,
                                               float* __restrict__ hall) {
    extern __shared__ __align__(16) float sm[];
    float4* ws4 = (float4*)sm;            // 8 rows x 256 float4 (32KB)
    float4* hs4 = (float4*)(sm + 8192);   // 16 batches x 256 float4 (64KB)
    int tid = threadIdx.x;
    int i0 = blockIdx.x * 8;

    // load + scale my 8 rows of W_h_eff
#pragma unroll
    for (int k = 0; k < 8; k++) {
        int f4 = k * 256 + tid;
        int row = f4 >> 8, c4 = f4 & 255;
        float4 v = *(const float4*)(Wh + (size_t)(i0 + row) * Dd + 4*c4);
        float s = g_scale[i0 + row];
        v.x *= s; v.y *= s; v.z *= s; v.w *= s;
        ws4[f4] = v;
    }

    int w = tid >> 5, l = tid & 31;
    int d0 = (w & 1) * 4, b0 = (w >> 1) * 4;
    volatile unsigned* vp = &g_arrive;

    for (int t = 0; t < Tt; t++) {
        const float* hin = g_h[t & 1];
        float* hout = g_h[(t & 1) ^ 1];
        // stage h (L2 reads: bypass stale L1)
#pragma unroll
        for (int k = 0; k < 16; k++) {
            int f4 = k * 256 + tid;
            hs4[f4] = __ldcg((const float4*)hin + f4);
        }
        __syncthreads();

        float acc[4][4];
#pragma unroll
        for (int d = 0; d < 4; d++)
#pragma unroll
            for (int b = 0; b < 4; b++) acc[d][b] = 0.f;
#pragma unroll
        for (int c = 0; c < 8; c++) {
            int f4 = c * 32 + l;
            float4 wv[4], hv[4];
#pragma unroll
            for (int d = 0; d < 4; d++) wv[d] = ws4[(d0 + d) * 256 + f4];
#pragma unroll
            for (int b = 0; b < 4; b++) hv[b] = hs4[(b0 + b) * 256 + f4];
#pragma unroll
            for (int d = 0; d < 4; d++)
#pragma unroll
                for (int b = 0; b < 4; b++)
                    acc[d][b] += wv[d].x*hv[b].x + wv[d].y*hv[b].y + wv[d].z*hv[b].z + wv[d].w*hv[b].w;
        }
#pragma unroll
        for (int o = 16; o > 0; o >>= 1)
#pragma unroll
            for (int d = 0; d < 4; d++)
#pragma unroll
                for (int b = 0; b < 4; b++)
                    acc[d][b] += __shfl_xor_sync(0xffffffffu, acc[d][b], o);

        if (l < 16) {
            int d = l & 3, b = l >> 2;
            int gi = i0 + d0 + d, gb = b0 + b;
            int row = (t * Bb + gb) * Dd + gi;
            float raw = acc[d][b] + g_pre[row];
            float h = tanhf(raw);
            float zv = z[row];
            float gate = zv / (1.f + expf(-zv));
            __stcg(&hout[gb * Dd + gi], h);
            hall[(t + 1) * (Bb*Dd) + gb * Dd + gi] = h;
            outp[row] = h * gate;
        }
        __syncthreads();
        if (tid == 0) {
            __threadfence();
            atomicAdd(&g_arrive, 1u);
            unsigned target = (unsigned)(t + 1) * NBLK;
            while (*vp < target) { }
            __threadfence();
        }
        __syncthreads();
    }
}

extern "C" void kernel_launch(void* const* d_in, const int* in_sizes, int n_in,
                              void* d_out, int out_size) {
    const float* x  = (const float*)d_in[0];
    const float* z  = (const float*)d_in[1];
    const float* h0 = (const float*)d_in[2];
    const float* Wx = (const float*)d_in[3];
    const float* Wh = (const float*)d_in[4];
    const float* lr = (const float*)d_in[5];
    const float* b  = (const float*)d_in[6];
    const float* u0 = (const float*)d_in[7];
    float* outp = (float*)d_out;
    float* hall = (float*)d_out + OUT_OFS;

    k_init<<<64, 256>>>(h0, hall);
    k_prep<<<1, 1024>>>(Wh, lr, u0);
    dim3 gg(Dd / 128, (Tt * Bb) / 128);
    k_gemm<<<gg, 256>>>(x, Wx, b);
    cudaFuncSetAttribute(k_recur, cudaFuncAttributeMaxDynamicSharedMemorySize, 98304);
    k_recur<<<NBLK, 256, 98304>>>(Wh, z, outp, hall);
}

// round 3
// speedup vs baseline: 1.0406x; 1.0406x over previous
#include <cuda_runtime.h>
#include <cuda_bf16.h>
#include <math.h>

#define Tt 1024
#define Bb 16
#define Dd 1024
#define NB 64
#define BD (Bb*Dd)
#define OUT_OFS (Tt*Bb*Dd)

__device__ __align__(16) float g_pre[Tt*Bb*Dd];
__device__ __align__(16) __nv_bfloat16 g_hA[2][64*32*16]; // [phase][kt*32+lane][8 hi | 8 lo]
__device__ __align__(16) float g_part[NB][Dd];
__device__ __align__(16) float g_vraw[Dd];
__device__ __align__(16) float g_uraw[Dd];
__device__ float g_ss[NB], g_ssu[NB];
__device__ unsigned g_arrive;

__device__ __forceinline__ void mma16816(float* c, const unsigned* a, const unsigned* b) {
    asm volatile(
        "mma.sync.aligned.m16n8k16.row.col.f32.bf16.bf16.f32 "
        "{%0,%1,%2,%3},{%4,%5,%6,%7},{%8,%9},{%0,%1,%2,%3};\n"
        : "+f"(c[0]), "+f"(c[1]), "+f"(c[2]), "+f"(c[3])
        : "r"(a[0]), "r"(a[1]), "r"(a[2]), "r"(a[3]), "r"(b[0]), "r"(b[1]));
}

__device__ __forceinline__ void gbar(unsigned* nbar) {
    (*nbar)++;
    __syncthreads();
    if (threadIdx.x == 0) {
        __threadfence();
        atomicAdd(&g_arrive, 1u);
        unsigned tgt = (*nbar) * NB;
        while (*(volatile unsigned*)&g_arrive < tgt) { }
        __threadfence();
    }
    __syncthreads();
}

// frag position of h element (b, j): writes hi at ret, lo at ret+8
__device__ __forceinline__ int frag_idx(int b, int j) {
    int kt = j >> 4, c = j & 15;
    int lt = ((b & 7) << 2) | ((c >> 1) & 3);
    int rg = (b >> 3) | ((c >> 3) << 1);
    return (kt * 32 + lt) * 16 + rg * 2 + (c & 1);
}

// ---- init: h_all[0], g_hA[0] frags of h0, barrier reset ----
__global__ void k_init(const float* __restrict__ h0, float* __restrict__ hall) {
    int e = blockIdx.x * 256 + threadIdx.x;  // grid 64x256 = 16384 = Bb*Dd
    if (e == 0) g_arrive = 0u;
    int b = e >> 10, j = e & 1023;
    float v = h0[e];
    hall[e] = v;
    __nv_bfloat16 hb = __float2bfloat16(v);
    float rem = v - __bfloat162float(hb);
    __nv_bfloat16 lb = __float2bfloat16(rem);
    int fi = frag_idx(b, j);
    g_hA[0][fi] = hb;
    g_hA[0][fi + 8] = lb;
}

// ---- GEMM: g_pre[m,n] = x[m,:].Wx[n,:] + b[n]  (fp32 SIMT 128x128x8) ----
__global__ void __launch_bounds__(256) k_gemm(const float* __restrict__ A,
                                              const float* __restrict__ Bw,
                                              const float* __restrict__ bias) {
    __shared__ float As[2][8][132], Bs[2][8][132];
    int tid = threadIdx.x;
    int m0 = blockIdx.y << 7, n0 = blockIdx.x << 7;
    int srow = tid >> 1, skq = (tid & 1) << 2;
    const float* ap = A  + (size_t)(m0 + srow) * Dd + skq;
    const float* bp = Bw + (size_t)(n0 + srow) * Dd + skq;
    int tx = tid & 15, ty = tid >> 4;

    float4 a4 = *(const float4*)ap;
    float4 b4 = *(const float4*)bp;
    As[0][skq+0][srow]=a4.x; As[0][skq+1][srow]=a4.y; As[0][skq+2][srow]=a4.z; As[0][skq+3][srow]=a4.w;
    Bs[0][skq+0][srow]=b4.x; Bs[0][skq+1][srow]=b4.y; Bs[0][skq+2][srow]=b4.z; Bs[0][skq+3][srow]=b4.w;
    __syncthreads();

    float acc[8][8];
#pragma unroll
    for (int r = 0; r < 8; r++)
#pragma unroll
        for (int c = 0; c < 8; c++) acc[r][c] = 0.f;

    for (int kt = 0; kt < 128; kt++) {
        int cur = kt & 1;
        float4 a4n, b4n;
        if (kt < 127) {
            a4n = *(const float4*)(ap + (size_t)(kt+1)*8);
            b4n = *(const float4*)(bp + (size_t)(kt+1)*8);
        }
#pragma unroll
        for (int k = 0; k < 8; k++) {
            float4 a0 = *(const float4*)&As[cur][k][ty<<2];
            float4 a1 = *(const float4*)&As[cur][k][64+(ty<<2)];
            float4 b0 = *(const float4*)&Bs[cur][k][tx<<2];
            float4 b1 = *(const float4*)&Bs[cur][k][64+(tx<<2)];
            float ar[8] = {a0.x,a0.y,a0.z,a0.w,a1.x,a1.y,a1.z,a1.w};
            float br[8] = {b0.x,b0.y,b0.z,b0.w,b1.x,b1.y,b1.z,b1.w};
#pragma unroll
            for (int r = 0; r < 8; r++)
#pragma unroll
                for (int c = 0; c < 8; c++) acc[r][c] += ar[r]*br[c];
        }
        if (kt < 127) {
            int nb = cur ^ 1;
            __syncthreads();
            As[nb][skq+0][srow]=a4n.x; As[nb][skq+1][srow]=a4n.y; As[nb][skq+2][srow]=a4n.z; As[nb][skq+3][srow]=a4n.w;
            Bs[nb][skq+0][srow]=b4n.x; Bs[nb][skq+1][srow]=b4n.y; Bs[nb][skq+2][srow]=b4n.z; Bs[nb][skq+3][srow]=b4n.w;
            __syncthreads();
        }
    }
    float4 ba0 = *(const float4*)&bias[n0 + (tx<<2)];
    float4 ba1 = *(const float4*)&bias[n0 + 64 + (tx<<2)];
#pragma unroll
    for (int r = 0; r < 8; r++) {
        int m = m0 + ((r < 4) ? (ty<<2)+r : 64+(ty<<2)+r-4);
        float* o = g_pre + (size_t)m * Dd + n0;
        float4 v0 = make_float4(acc[r][0]+ba0.x, acc[r][1]+ba0.y, acc[r][2]+ba0.z, acc[r][3]+ba0.w);
        float4 v1 = make_float4(acc[r][4]+ba1.x, acc[r][5]+ba1.y, acc[r][6]+ba1.z, acc[r][7]+ba1.w);
        *(float4*)(o + (tx<<2)) = v0;
        *(float4*)(o + 64 + (tx<<2)) = v1;
    }
}

// ---- persistent: power iteration prologue + mma recurrence. 64 blocks x 256 ----
__global__ void __launch_bounds__(256) k_recur(const float* __restrict__ Wh,
                                               const float* __restrict__ lr,
                                               const float* __restrict__ u0,
                                               const float* __restrict__ z,
                                               float* __restrict__ outp,
                                               float* __restrict__ hall) {
    __shared__ float sred[8 * 256];   // 8KB, reused by prologue
    __shared__ float s_u[16];
    int tid = threadIdx.x, w = tid >> 5, lane = tid & 31, blk = blockIdx.x;
    unsigned nbar = 0;

    // ================= power iteration (3 iters) =================
    float invu = 1.f, ssu = 0.f;
    for (int it = 0; it < 3; it++) {
        // pass1: g_part[blk][:] = (Wh rows blk*16..+16)^T @ u
        if (tid < 16) {
            float uu = (it == 0) ? u0[blk*16 + tid] : __ldcg(&g_uraw[blk*16 + tid]) * invu;
            s_u[tid] = uu;
        }
        __syncthreads();
        {
            float4 acc = make_float4(0.f, 0.f, 0.f, 0.f);
            const float* wp = Wh + (size_t)(blk*16) * Dd + tid*4;
#pragma unroll
            for (int r = 0; r < 16; r++) {
                float uu = s_u[r];
                float4 wv = *(const float4*)(wp + (size_t)r * Dd);
                acc.x += uu*wv.x; acc.y += uu*wv.y; acc.z += uu*wv.z; acc.w += uu*wv.w;
            }
            *(float4*)&g_part[blk][tid*4] = acc;
        }
        gbar(&nbar);
        // pass1b: sum partials for cols blk*16..+16, compute ||v||^2 partial
        {
            int c = blk*16 + (tid & 15);
            int p0 = tid >> 4;
            float v = 0.f;
#pragma unroll
            for (int q = 0; q < 4; q++) v += __ldcg(&g_part[p0 + q*16][c]);
            sred[p0 * 16 + (tid & 15)] = v;
            __syncthreads();
            if (tid < 16) {
                float s = 0.f;
#pragma unroll
                for (int p = 0; p < 16; p++) s += sred[p*16 + tid];
                g_vraw[blk*16 + tid] = s;
                float ss = s * s;
#pragma unroll
                for (int o = 8; o > 0; o >>= 1) ss += __shfl_xor_sync(0xffffu, ss, o);
                if (tid == 0) g_ss[blk] = ss;
            }
        }
        gbar(&nbar);
        float ssv = 0.f;
#pragma unroll
        for (int q = 0; q < NB; q++) ssv += __ldcg(&g_ss[q]);
        float invv = 1.f / (sqrtf(ssv) + 1e-8f);
        __syncthreads();
        // pass2: u_raw rows blk*16..+16 = Wh @ v
        {
            float* sv = sred;  // 1024 floats
            for (int q = tid; q < Dd; q += 256) sv[q] = __ldcg(&g_vraw[q]) * invv;
            __syncthreads();
            float ro[2];
#pragma unroll
            for (int rr = 0; rr < 2; rr++) {
                int row = blk*16 + w*2 + rr;
                const float4* wp = (const float4*)(Wh + (size_t)row * Dd);
                float acc = 0.f;
#pragma unroll
                for (int q = 0; q < 8; q++) {
                    float4 a = wp[q*32 + lane];
                    float4 b = *(const float4*)&sv[(q*32 + lane)*4];
                    acc += a.x*b.x + a.y*b.y + a.z*b.z + a.w*b.w;
                }
#pragma unroll
                for (int o = 16; o > 0; o >>= 1) acc += __shfl_xor_sync(0xffffffffu, acc, o);
                ro[rr] = acc;
                if (lane == 0) g_uraw[row] = acc;
            }
            __syncthreads();
            if (lane == 0) { sred[w*2] = ro[0]; sred[w*2+1] = ro[1]; }
            __syncthreads();
            if (tid < 16) {
                float x = sred[tid];
                float ss = x * x;
#pragma unroll
                for (int o = 8; o > 0; o >>= 1) ss += __shfl_xor_sync(0xffffu, ss, o);
                if (tid == 0) g_ssu[blk] = ss;
            }
        }
        gbar(&nbar);
        ssu = 0.f;
#pragma unroll
        for (int q = 0; q < NB; q++) ssu += __ldcg(&g_ssu[q]);
        invu = 1.f / (sqrtf(ssu) + 1e-8f);
        __syncthreads();
    }
    float sigma = ssu / (sqrtf(ssu) + 1e-8f);

    // ================= build W_h_eff fragments in registers =================
    int i0 = blk * 16;
    float scl[2];
#pragma unroll
    for (int nt = 0; nt < 2; nt++) {
        int d = i0 + nt*8 + (lane >> 2);
        float rad = 0.999f / (1.f + expf(-lr[d]));
        scl[nt] = rad / (sigma + 1e-8f);
    }
    unsigned WHI[8][2][2], WLO[8][2][2];
#pragma unroll
    for (int k8 = 0; k8 < 8; k8++)
#pragma unroll
        for (int nt = 0; nt < 2; nt++)
#pragma unroll
            for (int r = 0; r < 2; r++) {
                int d = i0 + nt*8 + (lane >> 2);
                int jb = (w*8 + k8)*16 + ((lane & 3) << 1) + r*8;
                float v0 = Wh[(size_t)d * Dd + jb]     * scl[nt];
                float v1 = Wh[(size_t)d * Dd + jb + 1] * scl[nt];
                __nv_bfloat162 hh = __floats2bfloat162_rn(v0, v1);
                float r0 = v0 - __bfloat162float(hh.x);
                float r1 = v1 - __bfloat162float(hh.y);
                __nv_bfloat162 ll = __floats2bfloat162_rn(r0, r1);
                WHI[k8][nt][r] = *(unsigned*)&hh;
                WLO[k8][nt][r] = *(unsigned*)&ll;
            }

    // ================= recurrence =================
    int gb = tid >> 4, dl = tid & 15, gd = i0 + dl;
    for (int t = 0; t < Tt; t++) {
        size_t row = ((size_t)(t*Bb) + gb) * Dd + gd;
        float pre_v = __ldcs(&g_pre[row]);   // overlap with mma
        float z_v   = __ldcs(&z[row]);

        const uint4* src = (const uint4*)g_hA[t & 1];
        float C0[4] = {0.f,0.f,0.f,0.f}, C1[4] = {0.f,0.f,0.f,0.f};
        uint4 bh[4], bl[4];
#pragma unroll
        for (int p = 0; p < 4; p++) {
            int kt = w*8 + p;
            bh[p] = __ldcg(src + (kt*32 + lane)*2);
            bl[p] = __ldcg(src + (kt*32 + lane)*2 + 1);
        }
#pragma unroll
        for (int k8 = 0; k8 < 8; k8++) {
            unsigned ah[4] = {bh[k8 & 3].x, bh[k8 & 3].y, bh[k8 & 3].z, bh[k8 & 3].w};
            unsigned al[4] = {bl[k8 & 3].x, bl[k8 & 3].y, bl[k8 & 3].z, bl[k8 & 3].w};
            if (k8 < 4) {
                int kt = w*8 + k8 + 4;
                bh[k8] = __ldcg(src + (kt*32 + lane)*2);
                bl[k8] = __ldcg(src + (kt*32 + lane)*2 + 1);
            }
            mma16816(C0, ah, WHI[k8][0]);
            mma16816(C0, al, WHI[k8][0]);
            mma16816(C0, ah, WLO[k8][0]);
            mma16816(C1, ah, WHI[k8][1]);
            mma16816(C1, al, WHI[k8][1]);
            mma16816(C1, ah, WLO[k8][1]);
        }
        // scatter partials: output o = b*16 + n_local
        {
            int r = lane >> 2, c2 = (lane & 3) << 1;
            float* dst = &sred[w * 256];
            dst[ r*16      + c2    ] = C0[0];
            dst[ r*16      + c2 + 1] = C0[1];
            dst[(r+8)*16   + c2    ] = C0[2];
            dst[(r+8)*16   + c2 + 1] = C0[3];
            dst[ r*16  + 8 + c2    ] = C1[0];
            dst[ r*16  + 8 + c2 + 1] = C1[1];
            dst[(r+8)*16+8 + c2    ] = C1[2];
            dst[(r+8)*16+8 + c2 + 1] = C1[3];
        }
        __syncthreads();
        float acc = pre_v;
#pragma unroll
        for (int ww = 0; ww < 8; ww++) acc += sred[ww*256 + tid];
        float h = tanhf(acc);
        float gate = z_v / (1.f + expf(-z_v));
        outp[row] = h * gate;
        hall[(size_t)(t+1) * BD + gb*Dd + gd] = h;
        __nv_bfloat16 hb = __float2bfloat16(h);
        float rem = h - __bfloat162float(hb);
        __nv_bfloat16 lb = __float2bfloat16(rem);
        int fi = frag_idx(gb, gd);
        __nv_bfloat16* df = &g_hA[(t+1) & 1][fi];
        df[0] = hb;
        df[8] = lb;
        gbar(&nbar);
    }
}

extern "C" void kernel_launch(void* const* d_in, const int* in_sizes, int n_in,
                              void* d_out, int out_size) {
    const float* x  = (const float*)d_in[0];
    const float* z  = (const float*)d_in[1];
    const float* h0 = (const float*)d_in[2];
    const float* Wx = (const float*)d_in[3];
    const float* Wh = (const float*)d_in[4];
    const float* lr = (const float*)d_in[5];
    const float* b  = (const float*)d_in[6];
    const float* u0 = (const float*)d_in[7];
    float* outp = (float*)d_out;
    float* hall = (float*)d_out + OUT_OFS;

    k_init<<<64, 256>>>(h0, hall);
    dim3 gg(Dd / 128, (Tt * Bb) / 128);
    k_gemm<<<gg, 256>>>(x, Wx, b);
    k_recur<<<NB, 256>>>(Wh, lr, u0, z, outp, hall);
}